// round 2
// baseline (speedup 1.0000x reference)
#include <cuda_runtime.h>
#include <cuda_bf16.h>
#include <cstddef>

// Problem constants
#define B_    8
#define H_    32
#define D_    128
#define DM_   4096
#define TC_   8192
#define TK_   8193
#define HD_   4096          // H*D
#define COLS3 12288         // 3*HD
#define SPLITK 8
#define KCH   512           // DM/SPLITK
#define CH    256           // keys per attention chunk
#define NCH   32            // TC/CH
#define NBH   256           // B*H
#define SCALE 0.08838834764831845f   // 1/sqrt(128)

#define OUT_SZ   (B_*DM_)                           // 32768
#define KCAT_SZ  ((size_t)NBH*TK_*D_)               // 268468224
#define KOFF     ((size_t)OUT_SZ)
#define VOFF     ((size_t)OUT_SZ + KCAT_SZ)

// ---------------- scratch (device globals; no allocation) ----------------
__device__ float g_qkv_part[SPLITK * B_ * COLS3];
__device__ float g_qkv[B_ * COLS3];
__device__ float g_pm[NBH * NCH];
__device__ float g_pl[NBH * NCH];
__device__ float g_pacc[(size_t)NBH * NCH * D_];
__device__ float g_o[B_ * HD_];
__device__ float g_o_part[SPLITK * B_ * HD_];

// ---------------- kernel 1: QKV projection, split-K, float4 cols ----------------
// grid (12, 8), block 256. Each thread: 4 consecutive columns, 8 batch rows.
__global__ void qkv_gemm(const float* __restrict__ x,
                         const float* __restrict__ Wq,
                         const float* __restrict__ Wk,
                         const float* __restrict__ Wv) {
    __shared__ float xs[KCH * 8];   // xs[kk*8 + r]
    const int split = blockIdx.y;
    const int col   = (blockIdx.x * 256 + threadIdx.x) * 4;
    const int k0    = split * KCH;

    for (int idx = threadIdx.x; idx < KCH * 8; idx += 256) {
        int kk = idx >> 3, r = idx & 7;
        xs[idx] = x[r * DM_ + k0 + kk];
    }
    __syncthreads();

    const int mat  = col >> 12;           // 0:q 1:k 2:v
    const int lcol = col & 4095;
    const float* W = (mat == 0) ? Wq : ((mat == 1) ? Wk : Wv);
    const float4* wp = (const float4*)(W + (size_t)k0 * HD_ + lcol);

    float4 acc[8];
    #pragma unroll
    for (int r = 0; r < 8; r++) acc[r] = make_float4(0.f, 0.f, 0.f, 0.f);

    #pragma unroll 4
    for (int kk = 0; kk < KCH; kk++) {
        float4 w4 = wp[(size_t)kk * (HD_ / 4)];
        #pragma unroll
        for (int r = 0; r < 8; r++) {
            float xv = xs[kk * 8 + r];
            acc[r].x += xv * w4.x; acc[r].y += xv * w4.y;
            acc[r].z += xv * w4.z; acc[r].w += xv * w4.w;
        }
    }
    float4* op = (float4*)(g_qkv_part + (size_t)split * (B_ * COLS3) + col);
    #pragma unroll
    for (int r = 0; r < 8; r++) op[r * (COLS3 / 4)] = acc[r];
}

__global__ void reduce_qkv() {
    int i = blockIdx.x * 256 + threadIdx.x;   // < 98304
    float s = 0.f;
    #pragma unroll
    for (int sp = 0; sp < SPLITK; sp++) s += g_qkv_part[(size_t)sp * (B_*COLS3) + i];
    g_qkv[i] = s;
}

// ---------------- kernel 2: fused cache-copy + flash attention chunk ----------------
// grid (NCH, NBH), block 256. Streaming loads/stores (zero-reuse data).
__global__ void attn_chunk(const float* __restrict__ kc,
                           const float* __restrict__ vc,
                           float* __restrict__ out) {
    __shared__ float s_q[D_];
    __shared__ float s_sc[CH];
    __shared__ float s_red[256];
    __shared__ float s_vacc[8 * D_];

    const int bh  = blockIdx.y;
    const int c   = blockIdx.x;
    const int tid = threadIdx.x;
    const int b   = bh >> 5;
    const int h   = bh & 31;

    if (tid < D_) s_q[tid] = g_qkv[b * COLS3 + h * D_ + tid];
    __syncthreads();

    const int t0   = c * CH;
    const int w    = tid >> 5;
    const int lane = tid & 31;
    const int dd   = lane * 4;

    const float qx = s_q[dd], qy = s_q[dd+1], qz = s_q[dd+2], qw = s_q[dd+3];

    // ---- K pass: dot + copy (streaming) ----
    const float4* kb  = (const float4*)(kc  + ((size_t)bh * TC_ + t0) * D_);
    float4*       okb = (float4*)(out + KOFF + ((size_t)bh * TK_ + t0) * D_);
    #pragma unroll 4
    for (int i = 0; i < CH / 8; i++) {
        int t = i * 8 + w;
        float4 k4 = __ldcs(kb + (size_t)t * 32 + lane);
        __stcs(okb + (size_t)t * 32 + lane, k4);
        float d = k4.x*qx + k4.y*qy + k4.z*qz + k4.w*qw;
        d += __shfl_down_sync(0xffffffffu, d, 16);
        d += __shfl_down_sync(0xffffffffu, d, 8);
        d += __shfl_down_sync(0xffffffffu, d, 4);
        d += __shfl_down_sync(0xffffffffu, d, 2);
        d += __shfl_down_sync(0xffffffffu, d, 1);
        if (lane == 0) s_sc[t] = d * SCALE;
    }
    __syncthreads();

    // ---- local max (256 scores, 256 threads) ----
    s_red[tid] = s_sc[tid];
    __syncthreads();
    for (int off = 128; off > 0; off >>= 1) {
        if (tid < off) s_red[tid] = fmaxf(s_red[tid], s_red[tid + off]);
        __syncthreads();
    }
    const float m = s_red[0];
    __syncthreads();

    // ---- exp + sum ----
    float e0 = __expf(s_sc[tid] - m);
    s_sc[tid] = e0;
    s_red[tid] = e0;
    __syncthreads();
    for (int off = 128; off > 0; off >>= 1) {
        if (tid < off) s_red[tid] += s_red[tid + off];
        __syncthreads();
    }
    const float l = s_red[0];

    // ---- V pass: weighted accumulate + copy (streaming) ----
    const float4* vb  = (const float4*)(vc  + ((size_t)bh * TC_ + t0) * D_);
    float4*       ovb = (float4*)(out + VOFF + ((size_t)bh * TK_ + t0) * D_);
    float ax = 0.f, ay = 0.f, az = 0.f, aw = 0.f;
    #pragma unroll 4
    for (int i = 0; i < CH / 8; i++) {
        int t = i * 8 + w;
        float p = s_sc[t];
        float4 v4 = __ldcs(vb + (size_t)t * 32 + lane);
        __stcs(ovb + (size_t)t * 32 + lane, v4);
        ax += p * v4.x; ay += p * v4.y; az += p * v4.z; aw += p * v4.w;
    }
    s_vacc[w * D_ + dd]     = ax;
    s_vacc[w * D_ + dd + 1] = ay;
    s_vacc[w * D_ + dd + 2] = az;
    s_vacc[w * D_ + dd + 3] = aw;
    __syncthreads();

    if (tid < D_) {
        float s = 0.f;
        #pragma unroll
        for (int g = 0; g < 8; g++) s += s_vacc[g * D_ + tid];
        g_pacc[((size_t)bh * NCH + c) * D_ + tid] = s;
        if (tid == 0) { g_pm[bh * NCH + c] = m; g_pl[bh * NCH + c] = l; }
    }
}

// ---------------- kernel 3: combine partials + new token + write new kv ----------------
// grid 256, block 512 (4 groups of 128 threads split the chunk loop).
__global__ void combine(float* __restrict__ out) {
    __shared__ float s_red[D_];
    __shared__ float s_snew;
    __shared__ float s_opart[4 * D_];
    const int bh  = blockIdx.x;
    const int tid = threadIdx.x;
    const int d   = tid & 127;
    const int g   = tid >> 7;
    const int b   = bh >> 5;
    const int h   = bh & 31;

    const float q  = g_qkv[b * COLS3 +           h * D_ + d];
    const float kn = g_qkv[b * COLS3 + HD_  +    h * D_ + d];
    const float vn = g_qkv[b * COLS3 + 2*HD_ +   h * D_ + d];

    if (g == 0) s_red[d] = q * kn;
    __syncthreads();
    if (g == 0) {
        for (int off = 64; off > 0; off >>= 1) {
            if (d < off) s_red[d] += s_red[d + off];
            __syncwarp(0xffffffffu);
            if (off > 32) __syncthreads();
        }
        if (d == 0) s_snew = s_red[0] * SCALE;
    }
    __syncthreads();
    const float snew = s_snew;

    float M = snew;
    #pragma unroll
    for (int c = 0; c < NCH; c++) M = fmaxf(M, g_pm[bh * NCH + c]);

    // each group accumulates 8 of the 32 chunks
    float og = 0.f;
    #pragma unroll
    for (int cc = 0; cc < NCH / 4; cc++) {
        int c = g + cc * 4;
        float wgt = __expf(g_pm[bh * NCH + c] - M);
        og += g_pacc[((size_t)bh * NCH + c) * D_ + d] * wgt;
    }
    s_opart[g * D_ + d] = og;
    __syncthreads();

    if (g == 0) {
        float en = __expf(snew - M);
        float L  = en;
        #pragma unroll
        for (int c = 0; c < NCH; c++)
            L += g_pl[bh * NCH + c] * __expf(g_pm[bh * NCH + c] - M);
        float o = en * vn + s_opart[d] + s_opart[D_ + d]
                + s_opart[2 * D_ + d] + s_opart[3 * D_ + d];
        g_o[b * HD_ + h * D_ + d] = o / L;

        out[KOFF + ((size_t)bh * TK_ + TC_) * D_ + d] = kn;
        out[VOFF + ((size_t)bh * TK_ + TC_) * D_ + d] = vn;
    }
}

// ---------------- kernel 4: output projection o @ Wo, split-K, float4 cols ----------------
// grid (4, 8), block 256.
__global__ void out_gemm(const float* __restrict__ Wo) {
    __shared__ float xs[KCH * 8];
    const int split = blockIdx.y;
    const int col   = (blockIdx.x * 256 + threadIdx.x) * 4;
    const int k0    = split * KCH;

    for (int idx = threadIdx.x; idx < KCH * 8; idx += 256) {
        int kk = idx >> 3, r = idx & 7;
        xs[idx] = g_o[r * HD_ + k0 + kk];
    }
    __syncthreads();

    const float4* wp = (const float4*)(Wo + (size_t)k0 * DM_ + col);
    float4 acc[8];
    #pragma unroll
    for (int r = 0; r < 8; r++) acc[r] = make_float4(0.f, 0.f, 0.f, 0.f);

    #pragma unroll 4
    for (int kk = 0; kk < KCH; kk++) {
        float4 w4 = wp[(size_t)kk * (DM_ / 4)];
        #pragma unroll
        for (int r = 0; r < 8; r++) {
            float xv = xs[kk * 8 + r];
            acc[r].x += xv * w4.x; acc[r].y += xv * w4.y;
            acc[r].z += xv * w4.z; acc[r].w += xv * w4.w;
        }
    }
    float4* op = (float4*)(g_o_part + (size_t)split * (B_ * DM_) + col);
    #pragma unroll
    for (int r = 0; r < 8; r++) op[r * (DM_ / 4)] = acc[r];
}

__global__ void reduce_out(float* __restrict__ out) {
    int i = blockIdx.x * 256 + threadIdx.x;   // < 32768
    float s = 0.f;
    #pragma unroll
    for (int sp = 0; sp < SPLITK; sp++) s += g_o_part[(size_t)sp * (B_*DM_) + i];
    out[i] = s;
}

// ---------------- launch ----------------
extern "C" void kernel_launch(void* const* d_in, const int* in_sizes, int n_in,
                              void* d_out, int out_size) {
    const float* x       = (const float*)d_in[0];
    const float* Wq      = (const float*)d_in[1];
    const float* Wk      = (const float*)d_in[2];
    const float* Wv      = (const float*)d_in[3];
    const float* Wo      = (const float*)d_in[4];
    const float* k_cache = (const float*)d_in[5];
    const float* v_cache = (const float*)d_in[6];
    float* out = (float*)d_out;

    qkv_gemm<<<dim3(12, SPLITK), 256>>>(x, Wq, Wk, Wv);
    reduce_qkv<<<(B_ * COLS3) / 256, 256>>>();
    attn_chunk<<<dim3(NCH, NBH), 256>>>(k_cache, v_cache, out);
    combine<<<NBH, 512>>>(out);
    out_gemm<<<dim3(4, SPLITK), 256>>>(Wo);
    reduce_out<<<(B_ * DM_) / 256, 256>>>(out);
}

// round 3
// speedup vs baseline: 1.1918x; 1.1918x over previous
#include <cuda_runtime.h>
#include <cuda_bf16.h>
#include <cstddef>

// Problem constants
#define B_    8
#define H_    32
#define D_    128
#define DM_   4096
#define TC_   8192
#define TK_   8193
#define HD_   4096          // H*D
#define COLS3 12288         // 3*HD
#define SPLITK 8
#define KCH   512           // DM/SPLITK
#define CH    512           // keys per attention chunk
#define NCH   16            // TC/CH
#define NBH   256           // B*H
#define SCALE 0.08838834764831845f   // 1/sqrt(128)

#define OUT_SZ   (B_*DM_)                           // 32768
#define KCAT_SZ  ((size_t)NBH*TK_*D_)               // 268468224
#define KOFF     ((size_t)OUT_SZ)
#define VOFF     ((size_t)OUT_SZ + KCAT_SZ)

// ---------------- scratch (device globals; no allocation) ----------------
__device__ float g_qkv_part[SPLITK * B_ * COLS3];
__device__ float g_qkv[B_ * COLS3];
__device__ float g_pm[NBH * NCH];
__device__ float g_pl[NBH * NCH];
__device__ float g_pacc[(size_t)NBH * NCH * D_];
__device__ float g_o[B_ * HD_];
__device__ float g_o_part[SPLITK * B_ * HD_];

// ---------------- kernel 1: QKV projection, split-K ----------------
// grid (48, 8), block 256. (identical to R1 / 819us baseline)
__global__ void qkv_gemm(const float* __restrict__ x,
                         const float* __restrict__ Wq,
                         const float* __restrict__ Wk,
                         const float* __restrict__ Wv) {
    __shared__ float xs[KCH * 8];   // xs[kk*8 + r]
    const int split = blockIdx.y;
    const int col   = blockIdx.x * 256 + threadIdx.x;
    const int k0    = split * KCH;

    for (int idx = threadIdx.x; idx < KCH * 8; idx += 256) {
        int kk = idx >> 3, r = idx & 7;
        xs[idx] = x[r * DM_ + k0 + kk];
    }
    __syncthreads();

    const int mat  = col >> 12;           // 0:q 1:k 2:v
    const int lcol = col & 4095;
    const float* W = (mat == 0) ? Wq : ((mat == 1) ? Wk : Wv);
    const float* wp = W + (size_t)k0 * HD_ + lcol;

    float acc0=0,acc1=0,acc2=0,acc3=0,acc4=0,acc5=0,acc6=0,acc7=0;
    #pragma unroll 4
    for (int kk = 0; kk < KCH; kk++) {
        float w = wp[(size_t)kk * HD_];
        float4 a  = *(const float4*)&xs[kk * 8];
        float4 b4 = *(const float4*)&xs[kk * 8 + 4];
        acc0 += a.x  * w; acc1 += a.y  * w; acc2 += a.z  * w; acc3 += a.w  * w;
        acc4 += b4.x * w; acc5 += b4.y * w; acc6 += b4.z * w; acc7 += b4.w * w;
    }
    float* op = g_qkv_part + (size_t)split * (B_ * COLS3) + col;
    op[0*COLS3]=acc0; op[1*COLS3]=acc1; op[2*COLS3]=acc2; op[3*COLS3]=acc3;
    op[4*COLS3]=acc4; op[5*COLS3]=acc5; op[6*COLS3]=acc6; op[7*COLS3]=acc7;
}

__global__ void reduce_qkv() {
    int i = blockIdx.x * 256 + threadIdx.x;   // < 98304
    float s = 0.f;
    #pragma unroll
    for (int sp = 0; sp < SPLITK; sp++) s += g_qkv_part[(size_t)sp * (B_*COLS3) + i];
    g_qkv[i] = s;
}

// ---------------- kernel 2: fused cache-copy + flash attention chunk ----------------
// grid (NCH, NBH), block 256. R1 structure, but K/V passes unrolled x4 with
// front-batched independent loads (MLP_p1=4 per warp).
__global__ void attn_chunk(const float* __restrict__ kc,
                           const float* __restrict__ vc,
                           float* __restrict__ out) {
    __shared__ float s_q[D_];
    __shared__ float s_sc[CH];
    __shared__ float s_red[256];
    __shared__ float s_vacc[8 * D_];

    const int bh  = blockIdx.y;
    const int c   = blockIdx.x;
    const int tid = threadIdx.x;
    const int b   = bh >> 5;
    const int h   = bh & 31;

    if (tid < D_) s_q[tid] = g_qkv[b * COLS3 + h * D_ + tid];
    __syncthreads();

    const int t0   = c * CH;
    const int w    = tid >> 5;
    const int lane = tid & 31;
    const int dd   = lane * 4;

    const float qx = s_q[dd], qy = s_q[dd+1], qz = s_q[dd+2], qw = s_q[dd+3];

    // ---- K pass: dot + copy, 4 loads in flight ----
    const float4* kb  = (const float4*)(kc  + ((size_t)bh * TC_ + t0) * D_);
    float4*       okb = (float4*)(out + KOFF + ((size_t)bh * TK_ + t0) * D_);
    for (int i = 0; i < CH / 8 / 4; i++) {
        const int tb = w * (CH / 8) + i * 4;
        float4 k0 = kb[(size_t)(tb + 0) * 32 + lane];
        float4 k1 = kb[(size_t)(tb + 1) * 32 + lane];
        float4 k2 = kb[(size_t)(tb + 2) * 32 + lane];
        float4 k3 = kb[(size_t)(tb + 3) * 32 + lane];
        okb[(size_t)(tb + 0) * 32 + lane] = k0;
        okb[(size_t)(tb + 1) * 32 + lane] = k1;
        okb[(size_t)(tb + 2) * 32 + lane] = k2;
        okb[(size_t)(tb + 3) * 32 + lane] = k3;
        float d0 = k0.x*qx + k0.y*qy + k0.z*qz + k0.w*qw;
        float d1 = k1.x*qx + k1.y*qy + k1.z*qz + k1.w*qw;
        float d2 = k2.x*qx + k2.y*qy + k2.z*qz + k2.w*qw;
        float d3 = k3.x*qx + k3.y*qy + k3.z*qz + k3.w*qw;
        #pragma unroll
        for (int off = 16; off > 0; off >>= 1) {
            d0 += __shfl_down_sync(0xffffffffu, d0, off);
            d1 += __shfl_down_sync(0xffffffffu, d1, off);
            d2 += __shfl_down_sync(0xffffffffu, d2, off);
            d3 += __shfl_down_sync(0xffffffffu, d3, off);
        }
        if (lane == 0) {
            s_sc[tb + 0] = d0 * SCALE;
            s_sc[tb + 1] = d1 * SCALE;
            s_sc[tb + 2] = d2 * SCALE;
            s_sc[tb + 3] = d3 * SCALE;
        }
    }
    __syncthreads();

    // ---- local max ----
    s_red[tid] = fmaxf(s_sc[tid], s_sc[tid + 256]);
    __syncthreads();
    for (int off = 128; off > 0; off >>= 1) {
        if (tid < off) s_red[tid] = fmaxf(s_red[tid], s_red[tid + off]);
        __syncthreads();
    }
    const float m = s_red[0];
    __syncthreads();

    // ---- exp + sum ----
    float e0 = __expf(s_sc[tid] - m);
    float e1 = __expf(s_sc[tid + 256] - m);
    s_sc[tid] = e0; s_sc[tid + 256] = e1;
    s_red[tid] = e0 + e1;
    __syncthreads();
    for (int off = 128; off > 0; off >>= 1) {
        if (tid < off) s_red[tid] += s_red[tid + off];
        __syncthreads();
    }
    const float l = s_red[0];

    // ---- V pass: weighted accumulate + copy, 4 loads in flight ----
    const float4* vb  = (const float4*)(vc  + ((size_t)bh * TC_ + t0) * D_);
    float4*       ovb = (float4*)(out + VOFF + ((size_t)bh * TK_ + t0) * D_);
    float ax = 0.f, ay = 0.f, az = 0.f, aw = 0.f;
    for (int i = 0; i < CH / 8 / 4; i++) {
        const int tb = w * (CH / 8) + i * 4;
        float4 v0 = vb[(size_t)(tb + 0) * 32 + lane];
        float4 v1 = vb[(size_t)(tb + 1) * 32 + lane];
        float4 v2 = vb[(size_t)(tb + 2) * 32 + lane];
        float4 v3 = vb[(size_t)(tb + 3) * 32 + lane];
        ovb[(size_t)(tb + 0) * 32 + lane] = v0;
        ovb[(size_t)(tb + 1) * 32 + lane] = v1;
        ovb[(size_t)(tb + 2) * 32 + lane] = v2;
        ovb[(size_t)(tb + 3) * 32 + lane] = v3;
        float p0 = s_sc[tb + 0], p1 = s_sc[tb + 1];
        float p2 = s_sc[tb + 2], p3 = s_sc[tb + 3];
        ax += p0 * v0.x; ay += p0 * v0.y; az += p0 * v0.z; aw += p0 * v0.w;
        ax += p1 * v1.x; ay += p1 * v1.y; az += p1 * v1.z; aw += p1 * v1.w;
        ax += p2 * v2.x; ay += p2 * v2.y; az += p2 * v2.z; aw += p2 * v2.w;
        ax += p3 * v3.x; ay += p3 * v3.y; az += p3 * v3.z; aw += p3 * v3.w;
    }
    s_vacc[w * D_ + dd]     = ax;
    s_vacc[w * D_ + dd + 1] = ay;
    s_vacc[w * D_ + dd + 2] = az;
    s_vacc[w * D_ + dd + 3] = aw;
    __syncthreads();

    if (tid < D_) {
        float s = 0.f;
        #pragma unroll
        for (int g = 0; g < 8; g++) s += s_vacc[g * D_ + tid];
        g_pacc[((size_t)bh * NCH + c) * D_ + tid] = s;
        if (tid == 0) { g_pm[bh * NCH + c] = m; g_pl[bh * NCH + c] = l; }
    }
}

// ---------------- kernel 3: combine partials + new token + write new kv ----------------
// grid 256, block 128. (identical to R1)
__global__ void combine(float* __restrict__ out) {
    __shared__ float s_red[D_];
    const int bh = blockIdx.x;
    const int d  = threadIdx.x;
    const int b  = bh >> 5;
    const int h  = bh & 31;

    const float q  = g_qkv[b * COLS3 +           h * D_ + d];
    const float kn = g_qkv[b * COLS3 + HD_  +    h * D_ + d];
    const float vn = g_qkv[b * COLS3 + 2*HD_ +   h * D_ + d];

    s_red[d] = q * kn;
    __syncthreads();
    for (int off = 64; off > 0; off >>= 1) {
        if (d < off) s_red[d] += s_red[d + off];
        __syncthreads();
    }
    const float snew = s_red[0] * SCALE;

    float M = snew;
    #pragma unroll
    for (int c = 0; c < NCH; c++) M = fmaxf(M, g_pm[bh * NCH + c]);

    float en = __expf(snew - M);
    float L  = en;
    float o  = en * vn;
    #pragma unroll
    for (int c = 0; c < NCH; c++) {
        float wgt = __expf(g_pm[bh * NCH + c] - M);
        L += g_pl[bh * NCH + c] * wgt;
        o += g_pacc[((size_t)bh * NCH + c) * D_ + d] * wgt;
    }
    g_o[b * HD_ + h * D_ + d] = o / L;

    out[KOFF + ((size_t)bh * TK_ + TC_) * D_ + d] = kn;
    out[VOFF + ((size_t)bh * TK_ + TC_) * D_ + d] = vn;
}

// ---------------- kernel 4: output projection o @ Wo, split-K ----------------
// grid (16, 8), block 256. (identical to R1)
__global__ void out_gemm(const float* __restrict__ Wo) {
    __shared__ float xs[KCH * 8];
    const int split = blockIdx.y;
    const int col   = blockIdx.x * 256 + threadIdx.x;
    const int k0    = split * KCH;

    for (int idx = threadIdx.x; idx < KCH * 8; idx += 256) {
        int kk = idx >> 3, r = idx & 7;
        xs[idx] = g_o[r * HD_ + k0 + kk];
    }
    __syncthreads();

    const float* wp = Wo + (size_t)k0 * DM_ + col;
    float acc0=0,acc1=0,acc2=0,acc3=0,acc4=0,acc5=0,acc6=0,acc7=0;
    #pragma unroll 4
    for (int kk = 0; kk < KCH; kk++) {
        float w = wp[(size_t)kk * DM_];
        float4 a  = *(const float4*)&xs[kk * 8];
        float4 b4 = *(const float4*)&xs[kk * 8 + 4];
        acc0 += a.x  * w; acc1 += a.y  * w; acc2 += a.z  * w; acc3 += a.w  * w;
        acc4 += b4.x * w; acc5 += b4.y * w; acc6 += b4.z * w; acc7 += b4.w * w;
    }
    float* op = g_o_part + (size_t)split * (B_ * DM_) + col;
    op[0*DM_]=acc0; op[1*DM_]=acc1; op[2*DM_]=acc2; op[3*DM_]=acc3;
    op[4*DM_]=acc4; op[5*DM_]=acc5; op[6*DM_]=acc6; op[7*DM_]=acc7;
}

__global__ void reduce_out(float* __restrict__ out) {
    int i = blockIdx.x * 256 + threadIdx.x;   // < 32768
    float s = 0.f;
    #pragma unroll
    for (int sp = 0; sp < SPLITK; sp++) s += g_o_part[(size_t)sp * (B_*DM_) + i];
    out[i] = s;
}

// ---------------- launch ----------------
extern "C" void kernel_launch(void* const* d_in, const int* in_sizes, int n_in,
                              void* d_out, int out_size) {
    const float* x       = (const float*)d_in[0];
    const float* Wq      = (const float*)d_in[1];
    const float* Wk      = (const float*)d_in[2];
    const float* Wv      = (const float*)d_in[3];
    const float* Wo      = (const float*)d_in[4];
    const float* k_cache = (const float*)d_in[5];
    const float* v_cache = (const float*)d_in[6];
    float* out = (float*)d_out;

    qkv_gemm<<<dim3(48, SPLITK), 256>>>(x, Wq, Wk, Wv);
    reduce_qkv<<<(B_ * COLS3) / 256, 256>>>();
    attn_chunk<<<dim3(NCH, NBH), 256>>>(k_cache, v_cache, out);
    combine<<<NBH, D_>>>(out);
    out_gemm<<<dim3(16, SPLITK), 256>>>(Wo);
    reduce_out<<<(B_ * DM_) / 256, 256>>>(out);
}

// round 4
// speedup vs baseline: 1.1998x; 1.0067x over previous
#include <cuda_runtime.h>
#include <cuda_bf16.h>
#include <cstddef>

// Problem constants
#define B_    8
#define H_    32
#define D_    128
#define DM_   4096
#define TC_   8192
#define TK_   8193
#define HD_   4096          // H*D
#define COLS3 12288         // 3*HD
#define SPLITK 8
#define KCH   512           // DM/SPLITK
#define CH    512           // keys per attention chunk
#define NCH   16            // TC/CH
#define NBH   256           // B*H
#define SCALE 0.08838834764831845f   // 1/sqrt(128)

#define OUT_SZ   (B_*DM_)                           // 32768
#define KCAT_SZ  ((size_t)NBH*TK_*D_)               // 268468224
#define KOFF     ((size_t)OUT_SZ)
#define VOFF     ((size_t)OUT_SZ + KCAT_SZ)

// ---------------- scratch (device globals; no allocation) ----------------
__device__ float g_qkv_part[SPLITK * B_ * COLS3];   // split-K partials [sp][b][col]
__device__ float g_pm[NBH * NCH];
__device__ float g_pl[NBH * NCH];
__device__ float g_pacc[(size_t)NBH * NCH * D_];
__device__ float g_o[B_ * HD_];
__device__ float g_o_part[SPLITK * B_ * HD_];

// ---------------- kernel 1: QKV projection, split-K ----------------
// grid (48, 8), block 256. (identical to R1 / 819us baseline)
__global__ void qkv_gemm(const float* __restrict__ x,
                         const float* __restrict__ Wq,
                         const float* __restrict__ Wk,
                         const float* __restrict__ Wv) {
    __shared__ float xs[KCH * 8];   // xs[kk*8 + r]
    const int split = blockIdx.y;
    const int col   = blockIdx.x * 256 + threadIdx.x;
    const int k0    = split * KCH;

    for (int idx = threadIdx.x; idx < KCH * 8; idx += 256) {
        int kk = idx >> 3, r = idx & 7;
        xs[idx] = x[r * DM_ + k0 + kk];
    }
    __syncthreads();

    const int mat  = col >> 12;           // 0:q 1:k 2:v
    const int lcol = col & 4095;
    const float* W = (mat == 0) ? Wq : ((mat == 1) ? Wk : Wv);
    const float* wp = W + (size_t)k0 * HD_ + lcol;

    float acc0=0,acc1=0,acc2=0,acc3=0,acc4=0,acc5=0,acc6=0,acc7=0;
    #pragma unroll 4
    for (int kk = 0; kk < KCH; kk++) {
        float w = wp[(size_t)kk * HD_];
        float4 a  = *(const float4*)&xs[kk * 8];
        float4 b4 = *(const float4*)&xs[kk * 8 + 4];
        acc0 += a.x  * w; acc1 += a.y  * w; acc2 += a.z  * w; acc3 += a.w  * w;
        acc4 += b4.x * w; acc5 += b4.y * w; acc6 += b4.z * w; acc7 += b4.w * w;
    }
    float* op = g_qkv_part + (size_t)split * (B_ * COLS3) + col;
    op[0*COLS3]=acc0; op[1*COLS3]=acc1; op[2*COLS3]=acc2; op[3*COLS3]=acc3;
    op[4*COLS3]=acc4; op[5*COLS3]=acc5; op[6*COLS3]=acc6; op[7*COLS3]=acc7;
}

// ---------------- kernel 2: fused cache-copy + flash attention chunk ----------------
// grid (NCH, NBH), block 256. R1 body; q is reduced from split-K partials here
// (removes the reduce_qkv kernel from the chain).
__global__ void attn_chunk(const float* __restrict__ kc,
                           const float* __restrict__ vc,
                           float* __restrict__ out) {
    __shared__ float s_q[D_];
    __shared__ float s_sc[CH];
    __shared__ float s_red[256];
    __shared__ float s_vacc[8 * D_];

    const int bh  = blockIdx.y;
    const int c   = blockIdx.x;
    const int tid = threadIdx.x;
    const int b   = bh >> 5;
    const int h   = bh & 31;

    if (tid < D_) {
        float s = 0.f;
        const float* qp = g_qkv_part + b * COLS3 + h * D_ + tid;
        #pragma unroll
        for (int sp = 0; sp < SPLITK; sp++) s += qp[(size_t)sp * (B_ * COLS3)];
        s_q[tid] = s;
    }
    __syncthreads();

    const int t0   = c * CH;
    const int w    = tid >> 5;
    const int lane = tid & 31;
    const int dd   = lane * 4;

    const float qx = s_q[dd], qy = s_q[dd+1], qz = s_q[dd+2], qw = s_q[dd+3];

    // ---- K pass: dot + copy ----
    const float* kbase  = kc  + ((size_t)bh * TC_ + t0) * D_;
    float*       okbase = out + KOFF + ((size_t)bh * TK_ + t0) * D_;
    for (int i = 0; i < CH / 8; i++) {
        int t = w * (CH / 8) + i;
        float4 k4 = *(const float4*)(kbase + (size_t)t * D_ + dd);
        *(float4*)(okbase + (size_t)t * D_ + dd) = k4;
        float d = k4.x*qx + k4.y*qy + k4.z*qz + k4.w*qw;
        d += __shfl_down_sync(0xffffffffu, d, 16);
        d += __shfl_down_sync(0xffffffffu, d, 8);
        d += __shfl_down_sync(0xffffffffu, d, 4);
        d += __shfl_down_sync(0xffffffffu, d, 2);
        d += __shfl_down_sync(0xffffffffu, d, 1);
        if (lane == 0) s_sc[t] = d * SCALE;
    }
    __syncthreads();

    // ---- local max ----
    s_red[tid] = fmaxf(s_sc[tid], s_sc[tid + 256]);
    __syncthreads();
    for (int off = 128; off > 0; off >>= 1) {
        if (tid < off) s_red[tid] = fmaxf(s_red[tid], s_red[tid + off]);
        __syncthreads();
    }
    const float m = s_red[0];
    __syncthreads();

    // ---- exp + sum ----
    float e0 = __expf(s_sc[tid] - m);
    float e1 = __expf(s_sc[tid + 256] - m);
    s_sc[tid] = e0; s_sc[tid + 256] = e1;
    s_red[tid] = e0 + e1;
    __syncthreads();
    for (int off = 128; off > 0; off >>= 1) {
        if (tid < off) s_red[tid] += s_red[tid + off];
        __syncthreads();
    }
    const float l = s_red[0];

    // ---- V pass: weighted accumulate + copy ----
    const float* vbase  = vc  + ((size_t)bh * TC_ + t0) * D_;
    float*       ovbase = out + VOFF + ((size_t)bh * TK_ + t0) * D_;
    float ax = 0.f, ay = 0.f, az = 0.f, aw = 0.f;
    for (int i = 0; i < CH / 8; i++) {
        int t = i * 8 + w;
        float p = s_sc[t];
        float4 v4 = *(const float4*)(vbase + (size_t)t * D_ + dd);
        *(float4*)(ovbase + (size_t)t * D_ + dd) = v4;
        ax += p * v4.x; ay += p * v4.y; az += p * v4.z; aw += p * v4.w;
    }
    s_vacc[w * D_ + dd]     = ax;
    s_vacc[w * D_ + dd + 1] = ay;
    s_vacc[w * D_ + dd + 2] = az;
    s_vacc[w * D_ + dd + 3] = aw;
    __syncthreads();

    if (tid < D_) {
        float s = 0.f;
        #pragma unroll
        for (int g = 0; g < 8; g++) s += s_vacc[g * D_ + tid];
        g_pacc[((size_t)bh * NCH + c) * D_ + tid] = s;
        if (tid == 0) { g_pm[bh * NCH + c] = m; g_pl[bh * NCH + c] = l; }
    }
}

// ---------------- kernel 3: combine partials + new token + write new kv ----------------
// grid 256, block 128. (R1 body; q/kn/vn reduced from split-K partials here)
__global__ void combine(float* __restrict__ out) {
    __shared__ float s_red[D_];
    const int bh = blockIdx.x;
    const int d  = threadIdx.x;
    const int b  = bh >> 5;
    const int h  = bh & 31;

    float q = 0.f, kn = 0.f, vn = 0.f;
    {
        const float* qp = g_qkv_part + b * COLS3 + h * D_ + d;
        #pragma unroll
        for (int sp = 0; sp < SPLITK; sp++) {
            const float* p = qp + (size_t)sp * (B_ * COLS3);
            q  += p[0];
            kn += p[HD_];
            vn += p[2 * HD_];
        }
    }

    s_red[d] = q * kn;
    __syncthreads();
    for (int off = 64; off > 0; off >>= 1) {
        if (d < off) s_red[d] += s_red[d + off];
        __syncthreads();
    }
    const float snew = s_red[0] * SCALE;

    float M = snew;
    #pragma unroll
    for (int c = 0; c < NCH; c++) M = fmaxf(M, g_pm[bh * NCH + c]);

    float en = __expf(snew - M);
    float L  = en;
    float o  = en * vn;
    #pragma unroll
    for (int c = 0; c < NCH; c++) {
        float wgt = __expf(g_pm[bh * NCH + c] - M);
        L += g_pl[bh * NCH + c] * wgt;
        o += g_pacc[((size_t)bh * NCH + c) * D_ + d] * wgt;
    }
    g_o[b * HD_ + h * D_ + d] = o / L;

    out[KOFF + ((size_t)bh * TK_ + TC_) * D_ + d] = kn;
    out[VOFF + ((size_t)bh * TK_ + TC_) * D_ + d] = vn;
}

// ---------------- kernel 4: output projection o @ Wo, split-K ----------------
// grid (16, 8), block 256. (identical to R1)
__global__ void out_gemm(const float* __restrict__ Wo) {
    __shared__ float xs[KCH * 8];
    const int split = blockIdx.y;
    const int col   = blockIdx.x * 256 + threadIdx.x;
    const int k0    = split * KCH;

    for (int idx = threadIdx.x; idx < KCH * 8; idx += 256) {
        int kk = idx >> 3, r = idx & 7;
        xs[idx] = g_o[r * HD_ + k0 + kk];
    }
    __syncthreads();

    const float* wp = Wo + (size_t)k0 * DM_ + col;
    float acc0=0,acc1=0,acc2=0,acc3=0,acc4=0,acc5=0,acc6=0,acc7=0;
    #pragma unroll 4
    for (int kk = 0; kk < KCH; kk++) {
        float w = wp[(size_t)kk * DM_];
        float4 a  = *(const float4*)&xs[kk * 8];
        float4 b4 = *(const float4*)&xs[kk * 8 + 4];
        acc0 += a.x  * w; acc1 += a.y  * w; acc2 += a.z  * w; acc3 += a.w  * w;
        acc4 += b4.x * w; acc5 += b4.y * w; acc6 += b4.z * w; acc7 += b4.w * w;
    }
    float* op = g_o_part + (size_t)split * (B_ * DM_) + col;
    op[0*DM_]=acc0; op[1*DM_]=acc1; op[2*DM_]=acc2; op[3*DM_]=acc3;
    op[4*DM_]=acc4; op[5*DM_]=acc5; op[6*DM_]=acc6; op[7*DM_]=acc7;
}

__global__ void reduce_out(float* __restrict__ out) {
    int i = blockIdx.x * 256 + threadIdx.x;   // < 32768
    float s = 0.f;
    #pragma unroll
    for (int sp = 0; sp < SPLITK; sp++) s += g_o_part[(size_t)sp * (B_*DM_) + i];
    out[i] = s;
}

// ---------------- launch ----------------
extern "C" void kernel_launch(void* const* d_in, const int* in_sizes, int n_in,
                              void* d_out, int out_size) {
    const float* x       = (const float*)d_in[0];
    const float* Wq      = (const float*)d_in[1];
    const float* Wk      = (const float*)d_in[2];
    const float* Wv      = (const float*)d_in[3];
    const float* Wo      = (const float*)d_in[4];
    const float* k_cache = (const float*)d_in[5];
    const float* v_cache = (const float*)d_in[6];
    float* out = (float*)d_out;

    qkv_gemm<<<dim3(48, SPLITK), 256>>>(x, Wq, Wk, Wv);
    attn_chunk<<<dim3(NCH, NBH), 256>>>(k_cache, v_cache, out);
    combine<<<NBH, D_>>>(out);
    out_gemm<<<dim3(16, SPLITK), 256>>>(Wo);
    reduce_out<<<(B_ * DM_) / 256, 256>>>(out);
}

// round 5
// speedup vs baseline: 1.3895x; 1.1581x over previous
#include <cuda_runtime.h>
#include <cuda_bf16.h>
#include <cstddef>

// Problem constants
#define B_    8
#define H_    32
#define D_    128
#define DM_   4096
#define TC_   8192
#define TK_   8193
#define HD_   4096          // H*D
#define COLS3 12288         // 3*HD
#define SPLITK 32
#define KCH   128           // DM/SPLITK
#define CH    512           // keys per attention chunk
#define NCH   16            // TC/CH
#define NBH   256           // B*H
#define SCALE 0.08838834764831845f   // 1/sqrt(128)

#define OUT_SZ   (B_*DM_)                           // 32768
#define KCAT_SZ  ((size_t)NBH*TK_*D_)               // 268468224
#define KOFF     ((size_t)OUT_SZ)
#define VOFF     ((size_t)OUT_SZ + KCAT_SZ)

// ---------------- scratch (device globals; no allocation) ----------------
__device__ float g_qkv_part[SPLITK * B_ * COLS3];   // 12.6 MB
__device__ float g_qkv[B_ * COLS3];
__device__ float g_pm[NBH * NCH];
__device__ float g_pl[NBH * NCH];
__device__ float g_pacc[(size_t)NBH * NCH * D_];
__device__ float g_o[B_ * HD_];
__device__ float g_o_part[SPLITK * B_ * HD_];       // 4 MB

// ---------------- kernel 1: QKV projection, split-K x32, 8 loads in flight ----------------
// grid (48, 32), block 256.
__global__ void qkv_gemm(const float* __restrict__ x,
                         const float* __restrict__ Wq,
                         const float* __restrict__ Wk,
                         const float* __restrict__ Wv) {
    __shared__ float xs[KCH * 8];   // xs[kk*8 + r]
    const int split = blockIdx.y;
    const int col   = blockIdx.x * 256 + threadIdx.x;
    const int k0    = split * KCH;

    for (int idx = threadIdx.x; idx < KCH * 8; idx += 256) {
        int kk = idx >> 3, r = idx & 7;
        xs[idx] = x[r * DM_ + k0 + kk];
    }
    __syncthreads();

    const int mat  = col >> 12;           // 0:q 1:k 2:v
    const int lcol = col & 4095;
    const float* W = (mat == 0) ? Wq : ((mat == 1) ? Wk : Wv);
    const float* wp = W + (size_t)k0 * HD_ + lcol;

    float acc[8];
    #pragma unroll
    for (int r = 0; r < 8; r++) acc[r] = 0.f;

    for (int kk = 0; kk < KCH; kk += 8) {
        float w[8];
        #pragma unroll
        for (int j = 0; j < 8; j++) w[j] = wp[(size_t)(kk + j) * HD_];
        #pragma unroll
        for (int j = 0; j < 8; j++) {
            #pragma unroll
            for (int r = 0; r < 8; r++) acc[r] += xs[(kk + j) * 8 + r] * w[j];
        }
    }
    float* op = g_qkv_part + (size_t)split * (B_ * COLS3) + col;
    #pragma unroll
    for (int r = 0; r < 8; r++) op[(size_t)r * COLS3] = acc[r];
}

__global__ void reduce_qkv() {
    int i = blockIdx.x * 256 + threadIdx.x;   // < 98304
    float s = 0.f;
    #pragma unroll
    for (int sp = 0; sp < SPLITK; sp++) s += g_qkv_part[(size_t)sp * (B_*COLS3) + i];
    g_qkv[i] = s;
}

// ---------------- kernel 2: fused cache-copy + flash attention chunk ----------------
// grid (NCH, NBH), block 256. (identical to R1 / 819us baseline body)
__global__ void attn_chunk(const float* __restrict__ kc,
                           const float* __restrict__ vc,
                           float* __restrict__ out) {
    __shared__ float s_q[D_];
    __shared__ float s_sc[CH];
    __shared__ float s_red[256];
    __shared__ float s_vacc[8 * D_];

    const int bh  = blockIdx.y;
    const int c   = blockIdx.x;
    const int tid = threadIdx.x;
    const int b   = bh >> 5;
    const int h   = bh & 31;

    if (tid < D_) s_q[tid] = g_qkv[b * COLS3 + h * D_ + tid];
    __syncthreads();

    const int t0   = c * CH;
    const int w    = tid >> 5;
    const int lane = tid & 31;
    const int dd   = lane * 4;

    const float qx = s_q[dd], qy = s_q[dd+1], qz = s_q[dd+2], qw = s_q[dd+3];

    // ---- K pass: dot + copy ----
    const float* kbase  = kc  + ((size_t)bh * TC_ + t0) * D_;
    float*       okbase = out + KOFF + ((size_t)bh * TK_ + t0) * D_;
    for (int i = 0; i < CH / 8; i++) {
        int t = w * (CH / 8) + i;
        float4 k4 = *(const float4*)(kbase + (size_t)t * D_ + dd);
        *(float4*)(okbase + (size_t)t * D_ + dd) = k4;
        float d = k4.x*qx + k4.y*qy + k4.z*qz + k4.w*qw;
        d += __shfl_down_sync(0xffffffffu, d, 16);
        d += __shfl_down_sync(0xffffffffu, d, 8);
        d += __shfl_down_sync(0xffffffffu, d, 4);
        d += __shfl_down_sync(0xffffffffu, d, 2);
        d += __shfl_down_sync(0xffffffffu, d, 1);
        if (lane == 0) s_sc[t] = d * SCALE;
    }
    __syncthreads();

    // ---- local max ----
    s_red[tid] = fmaxf(s_sc[tid], s_sc[tid + 256]);
    __syncthreads();
    for (int off = 128; off > 0; off >>= 1) {
        if (tid < off) s_red[tid] = fmaxf(s_red[tid], s_red[tid + off]);
        __syncthreads();
    }
    const float m = s_red[0];
    __syncthreads();

    // ---- exp + sum ----
    float e0 = __expf(s_sc[tid] - m);
    float e1 = __expf(s_sc[tid + 256] - m);
    s_sc[tid] = e0; s_sc[tid + 256] = e1;
    s_red[tid] = e0 + e1;
    __syncthreads();
    for (int off = 128; off > 0; off >>= 1) {
        if (tid < off) s_red[tid] += s_red[tid + off];
        __syncthreads();
    }
    const float l = s_red[0];

    // ---- V pass: weighted accumulate + copy ----
    const float* vbase  = vc  + ((size_t)bh * TC_ + t0) * D_;
    float*       ovbase = out + VOFF + ((size_t)bh * TK_ + t0) * D_;
    float ax = 0.f, ay = 0.f, az = 0.f, aw = 0.f;
    for (int i = 0; i < CH / 8; i++) {
        int t = i * 8 + w;
        float p = s_sc[t];
        float4 v4 = *(const float4*)(vbase + (size_t)t * D_ + dd);
        *(float4*)(ovbase + (size_t)t * D_ + dd) = v4;
        ax += p * v4.x; ay += p * v4.y; az += p * v4.z; aw += p * v4.w;
    }
    s_vacc[w * D_ + dd]     = ax;
    s_vacc[w * D_ + dd + 1] = ay;
    s_vacc[w * D_ + dd + 2] = az;
    s_vacc[w * D_ + dd + 3] = aw;
    __syncthreads();

    if (tid < D_) {
        float s = 0.f;
        #pragma unroll
        for (int g = 0; g < 8; g++) s += s_vacc[g * D_ + tid];
        g_pacc[((size_t)bh * NCH + c) * D_ + tid] = s;
        if (tid == 0) { g_pm[bh * NCH + c] = m; g_pl[bh * NCH + c] = l; }
    }
}

// ---------------- kernel 3: combine partials + new token + write new kv ----------------
// grid 256, block 128. (identical to R1)
__global__ void combine(float* __restrict__ out) {
    __shared__ float s_red[D_];
    const int bh = blockIdx.x;
    const int d  = threadIdx.x;
    const int b  = bh >> 5;
    const int h  = bh & 31;

    const float q  = g_qkv[b * COLS3 +           h * D_ + d];
    const float kn = g_qkv[b * COLS3 + HD_  +    h * D_ + d];
    const float vn = g_qkv[b * COLS3 + 2*HD_ +   h * D_ + d];

    s_red[d] = q * kn;
    __syncthreads();
    for (int off = 64; off > 0; off >>= 1) {
        if (d < off) s_red[d] += s_red[d + off];
        __syncthreads();
    }
    const float snew = s_red[0] * SCALE;

    float M = snew;
    #pragma unroll
    for (int c = 0; c < NCH; c++) M = fmaxf(M, g_pm[bh * NCH + c]);

    float en = __expf(snew - M);
    float L  = en;
    float o  = en * vn;
    #pragma unroll
    for (int c = 0; c < NCH; c++) {
        float wgt = __expf(g_pm[bh * NCH + c] - M);
        L += g_pl[bh * NCH + c] * wgt;
        o += g_pacc[((size_t)bh * NCH + c) * D_ + d] * wgt;
    }
    g_o[b * HD_ + h * D_ + d] = o / L;

    out[KOFF + ((size_t)bh * TK_ + TC_) * D_ + d] = kn;
    out[VOFF + ((size_t)bh * TK_ + TC_) * D_ + d] = vn;
}

// ---------------- kernel 4: output projection o @ Wo, split-K x32 ----------------
// grid (16, 32), block 256.
__global__ void out_gemm(const float* __restrict__ Wo) {
    __shared__ float xs[KCH * 8];
    const int split = blockIdx.y;
    const int col   = blockIdx.x * 256 + threadIdx.x;
    const int k0    = split * KCH;

    for (int idx = threadIdx.x; idx < KCH * 8; idx += 256) {
        int kk = idx >> 3, r = idx & 7;
        xs[idx] = g_o[r * HD_ + k0 + kk];
    }
    __syncthreads();

    const float* wp = Wo + (size_t)k0 * DM_ + col;
    float acc[8];
    #pragma unroll
    for (int r = 0; r < 8; r++) acc[r] = 0.f;

    for (int kk = 0; kk < KCH; kk += 8) {
        float w[8];
        #pragma unroll
        for (int j = 0; j < 8; j++) w[j] = wp[(size_t)(kk + j) * DM_];
        #pragma unroll
        for (int j = 0; j < 8; j++) {
            #pragma unroll
            for (int r = 0; r < 8; r++) acc[r] += xs[(kk + j) * 8 + r] * w[j];
        }
    }
    float* op = g_o_part + (size_t)split * (B_ * DM_) + col;
    #pragma unroll
    for (int r = 0; r < 8; r++) op[(size_t)r * DM_] = acc[r];
}

__global__ void reduce_out(float* __restrict__ out) {
    int i = blockIdx.x * 256 + threadIdx.x;   // < 32768
    float s = 0.f;
    #pragma unroll
    for (int sp = 0; sp < SPLITK; sp++) s += g_o_part[(size_t)sp * (B_*DM_) + i];
    out[i] = s;
}

// ---------------- launch ----------------
extern "C" void kernel_launch(void* const* d_in, const int* in_sizes, int n_in,
                              void* d_out, int out_size) {
    const float* x       = (const float*)d_in[0];
    const float* Wq      = (const float*)d_in[1];
    const float* Wk      = (const float*)d_in[2];
    const float* Wv      = (const float*)d_in[3];
    const float* Wo      = (const float*)d_in[4];
    const float* k_cache = (const float*)d_in[5];
    const float* v_cache = (const float*)d_in[6];
    float* out = (float*)d_out;

    qkv_gemm<<<dim3(48, SPLITK), 256>>>(x, Wq, Wk, Wv);
    reduce_qkv<<<(B_ * COLS3) / 256, 256>>>();
    attn_chunk<<<dim3(NCH, NBH), 256>>>(k_cache, v_cache, out);
    combine<<<NBH, D_>>>(out);
    out_gemm<<<dim3(16, SPLITK), 256>>>(Wo);
    reduce_out<<<(B_ * DM_) / 256, 256>>>(out);
}